// round 12
// baseline (speedup 1.0000x reference)
#include <cuda_runtime.h>
#include <cuda_fp16.h>

// IntDVF scaling-and-squaring, packed-half4 + z-shifted dual-copy version.
// ddf0 = dvf / 2^7 ; repeat 7x: ddf = ddf + warp(ddf, ddf)
//
// Field stored as 4x fp16 (x,y,z,pad)=8B/voxel, in TWO copies per buffer:
//   copy A (voxels [0,NVOX))         : A[i] = val[i]
//   copy B (voxels [NVOX,2*NVOX))    : B[i] = val[i+1]   (z-shifted by 1)
// A trilinear z-pair (jz, jz+1) is one aligned LDG.128 from copy (jz&1 ? B : A)
// at even base jz-(jz&1)  ->  4 gather loads per voxel instead of 8.
// All arithmetic fp32; fp16 is storage only. Final step writes fp32 AoS.

#define D     128
#define D2    (D * D)
#define D3    (D * D * D)
#define NVOX  (2 * D3)          // 4,194,304 voxels (batch=2)
#define NT    256

// Ping-pong buffers, each = 2*NVOX uint2 voxels (copies A+B), 16B-aligned.
__device__ uint4 g_a[(size_t)NVOX];   // 67 MB
__device__ uint4 g_b[(size_t)NVOX];   // 67 MB

__device__ __forceinline__ uint2 packh4(float x, float y, float z) {
    __half2 xy = __floats2half2_rn(x, y);
    __half2 zw = __floats2half2_rn(z, 0.0f);
    uint2 r;
    r.x = *(const unsigned int*)&xy;
    r.y = *(const unsigned int*)&zw;
    return r;
}

__device__ __forceinline__ void unpackh4(unsigned int vx, unsigned int vy,
                                         float& x, float& y, float& z) {
    __half2 xy = *(const __half2*)&vx;
    __half2 zw = *(const __half2*)&vy;
    float2 f = __half22float2(xy);
    x = f.x;
    y = f.y;
    z = __half2float(__low2half(zw));
}

__global__ __launch_bounds__(NT)
void pack_h4(const float* __restrict__ in, uint4* __restrict__ out) {
    int i = blockIdx.x * NT + threadIdx.x;
    size_t o = (size_t)i * 3;
    uint2 v = packh4(in[o + 0], in[o + 1], in[o + 2]);
    uint2* o2 = (uint2*)out;
    o2[i] = v;                                  // copy A
    if (i) o2[NVOX + i - 1] = v;                // copy B (shifted by 1)
}

template<bool OUT_F32_AOS, bool SCALED>
__global__ __launch_bounds__(NT)
void intdvf_step(const uint4* __restrict__ srcp, void* __restrict__ dst_raw,
                 float scale) {
    int idx = blockIdx.x * NT + threadIdx.x;
    int z = idx & (D - 1);
    int y = (idx >> 7) & (D - 1);
    int x = (idx >> 14) & (D - 1);
    int bb = (idx >> 21) * D3;

    const uint2* __restrict__ s2 = (const uint2*)srcp;

    float rx, ry, rz;
    {
        uint2 c = __ldg(s2 + idx);              // center from copy A
        unpackh4(c.x, c.y, rx, ry, rz);
    }

    float lx = (float)x + (SCALED ? rx * scale : rx);
    float ly = (float)y + (SCALED ? ry * scale : ry);
    float lz = (float)z + (SCALED ? rz * scale : rz);

    // Clamp the location (equivalent to reference's index clipping).
    lx = fminf(fmaxf(lx, 0.0f), 127.0f);
    ly = fminf(fmaxf(ly, 0.0f), 127.0f);
    lz = fminf(fmaxf(lz, 0.0f), 127.0f);

    float fx = floorf(lx), fy = floorf(ly), fz = floorf(lz);
    float wx1 = lx - fx, wy1 = ly - fy, wz1 = lz - fz;
    float wx0 = 1.0f - wx1, wy0 = 1.0f - wy1, wz0 = 1.0f - wz1;

    int jx = (int)fx, jy = (int)fy, jz = (int)fz;   // all in [0,127]

    // Row offsets for the 4 (x,y) corners (x/y clamped via conditional offset).
    int offx = (jx < D - 1) ? D2 : 0;
    int offy = (jy < D - 1) ? D  : 0;
    int r00 = bb + (jx << 14) + (jy << 7);
    int r01 = r00 + offy;
    int r10 = r00 + offx;
    int r11 = r10 + offy;

    // z-pair column: even base within copy A (jz even) or copy B (jz odd).
    int zpar = jz & 1;
    int zcol = jz - zpar + (zpar ? NVOX : 0);

    // 4 gather LDG.128s; each carries BOTH z taps (lo = wz0 lane, hi = wz1 lane).
    uint4 q00 = __ldg(srcp + ((r00 + zcol) >> 1));
    uint4 q01 = __ldg(srcp + ((r01 + zcol) >> 1));
    uint4 q10 = __ldg(srcp + ((r10 + zcol) >> 1));
    uint4 q11 = __ldg(srcp + ((r11 + zcol) >> 1));

    float w00 = wx0 * wy0, w01 = wx0 * wy1, w10 = wx1 * wy0, w11 = wx1 * wy1;

    float ax = 0.f, ay = 0.f, az = 0.f, tx, ty, tz;
    float wl, wh;
    wl = w00 * wz0; wh = w00 * wz1;
    unpackh4(q00.x, q00.y, tx, ty, tz); ax = fmaf(wl, tx, ax); ay = fmaf(wl, ty, ay); az = fmaf(wl, tz, az);
    unpackh4(q00.z, q00.w, tx, ty, tz); ax = fmaf(wh, tx, ax); ay = fmaf(wh, ty, ay); az = fmaf(wh, tz, az);
    wl = w01 * wz0; wh = w01 * wz1;
    unpackh4(q01.x, q01.y, tx, ty, tz); ax = fmaf(wl, tx, ax); ay = fmaf(wl, ty, ay); az = fmaf(wl, tz, az);
    unpackh4(q01.z, q01.w, tx, ty, tz); ax = fmaf(wh, tx, ax); ay = fmaf(wh, ty, ay); az = fmaf(wh, tz, az);
    wl = w10 * wz0; wh = w10 * wz1;
    unpackh4(q10.x, q10.y, tx, ty, tz); ax = fmaf(wl, tx, ax); ay = fmaf(wl, ty, ay); az = fmaf(wl, tz, az);
    unpackh4(q10.z, q10.w, tx, ty, tz); ax = fmaf(wh, tx, ax); ay = fmaf(wh, ty, ay); az = fmaf(wh, tz, az);
    wl = w11 * wz0; wh = w11 * wz1;
    unpackh4(q11.x, q11.y, tx, ty, tz); ax = fmaf(wl, tx, ax); ay = fmaf(wl, ty, ay); az = fmaf(wl, tz, az);
    unpackh4(q11.z, q11.w, tx, ty, tz); ax = fmaf(wh, tx, ax); ay = fmaf(wh, ty, ay); az = fmaf(wh, tz, az);

    float ox, oy, oz;
    if (SCALED) {
        ox = scale * (rx + ax);
        oy = scale * (ry + ay);
        oz = scale * (rz + az);
    } else {
        ox = rx + ax;
        oy = ry + ay;
        oz = rz + az;
    }

    if (OUT_F32_AOS) {
        float* dst = (float*)dst_raw;
        size_t o = (size_t)idx * 3;
        dst[o + 0] = ox;
        dst[o + 1] = oy;
        dst[o + 2] = oz;
    } else {
        uint2 v = packh4(ox, oy, oz);
        uint2* d2 = (uint2*)dst_raw;
        d2[idx] = v;                            // copy A
        if (idx) d2[NVOX + idx - 1] = v;        // copy B (shifted by 1)
    }
}

extern "C" void kernel_launch(void* const* d_in, const int* in_sizes, int n_in,
                              void* d_out, int out_size) {
    const float* dvf = (const float*)d_in[0];

    uint4* A = nullptr;
    uint4* Bf = nullptr;
    cudaGetSymbolAddress((void**)&A,  g_a);
    cudaGetSymbolAddress((void**)&Bf, g_b);

    const int nblocks = NVOX / NT;              // 16384
    const float s0 = 1.0f / 128.0f;             // 1 / 2^NUM_STEPS

    pack_h4<<<nblocks, NT>>>(dvf, A);

    intdvf_step<false, true ><<<nblocks, NT>>>(A,  Bf,   s0);   // step 1 (fused /128)
    intdvf_step<false, false><<<nblocks, NT>>>(Bf, A,    1.0f); // step 2
    intdvf_step<false, false><<<nblocks, NT>>>(A,  Bf,   1.0f); // step 3
    intdvf_step<false, false><<<nblocks, NT>>>(Bf, A,    1.0f); // step 4
    intdvf_step<false, false><<<nblocks, NT>>>(A,  Bf,   1.0f); // step 5
    intdvf_step<false, false><<<nblocks, NT>>>(Bf, A,    1.0f); // step 6
    intdvf_step<true,  false><<<nblocks, NT>>>(A,  d_out, 1.0f); // step 7 -> fp32 AoS
}

// round 13
// speedup vs baseline: 1.3506x; 1.3506x over previous
#include <cuda_runtime.h>
#include <cuda_fp16.h>

// IntDVF scaling-and-squaring, packed-half4 (8B/voxel), ALU-trimmed addressing.
// ddf0 = dvf / 2^7 ; repeat 7x: ddf = ddf + warp(ddf, ddf)
//
// Field stored as 4x fp16 (x,y,z,pad) = 8B/voxel (33.5 MB/buffer -> both
// ping-pong buffers L2-resident). One LDG.64 per trilinear corner.
// Location clamping + conditional offsets replace per-index clipping
// (mathematically identical to the reference). fp32 arithmetic throughout;
// fp16 is storage only. Final step writes fp32 AoS to d_out.

#define D     128
#define D2    (D * D)
#define D3    (D * D * D)
#define NVOX  (2 * D3)          // 4,194,304 voxels (batch=2)
#define NT    256

// Two 33.5 MB packed ping-pong buffers (both L2-resident together).
__device__ uint2 g_a[(size_t)NVOX];
__device__ uint2 g_b[(size_t)NVOX];

__device__ __forceinline__ uint2 packh4(float x, float y, float z) {
    __half2 xy = __floats2half2_rn(x, y);
    __half2 zw = __floats2half2_rn(z, 0.0f);
    uint2 r;
    r.x = *(const unsigned int*)&xy;
    r.y = *(const unsigned int*)&zw;
    return r;
}

__device__ __forceinline__ void unpackh4(uint2 v, float& x, float& y, float& z) {
    __half2 xy = *(const __half2*)&v.x;
    __half2 zw = *(const __half2*)&v.y;
    float2 f = __half22float2(xy);
    x = f.x;
    y = f.y;
    z = __half2float(__low2half(zw));
}

__global__ __launch_bounds__(NT)
void pack_h4(const float* __restrict__ in, uint2* __restrict__ out) {
    int i = blockIdx.x * NT + threadIdx.x;
    size_t o = (size_t)i * 3;
    out[i] = packh4(in[o + 0], in[o + 1], in[o + 2]);
}

template<bool OUT_F32_AOS, bool SCALED>
__global__ __launch_bounds__(NT)
void intdvf_step(const uint2* __restrict__ src, void* __restrict__ dst_raw,
                 float scale) {
    int idx = blockIdx.x * NT + threadIdx.x;
    int z = idx & (D - 1);
    int y = (idx >> 7) & (D - 1);
    int x = (idx >> 14) & (D - 1);
    int bb = (idx >> 21) * D3;

    float rx, ry, rz;
    unpackh4(__ldg(src + idx), rx, ry, rz);   // coalesced 8B center read

    float lx = (float)x + (SCALED ? rx * scale : rx);
    float ly = (float)y + (SCALED ? ry * scale : ry);
    float lz = (float)z + (SCALED ? rz * scale : rz);

    // Clamp the location (equivalent to the reference's index clipping).
    lx = fminf(fmaxf(lx, 0.0f), 127.0f);
    ly = fminf(fmaxf(ly, 0.0f), 127.0f);
    lz = fminf(fmaxf(lz, 0.0f), 127.0f);

    float fx = floorf(lx), fy = floorf(ly), fz = floorf(lz);
    float wx1 = lx - fx, wy1 = ly - fy, wz1 = lz - fz;
    float wx0 = 1.0f - wx1, wy0 = 1.0f - wy1, wz0 = 1.0f - wz1;

    int jx = (int)fx, jy = (int)fy, jz = (int)fz;   // all in [0,127]

    // Upper-edge clamp via conditional strides (jz==127 etc. -> weight w*1==0,
    // tap collapses onto the lower corner, exactly as the reference).
    int offx = (jx < D - 1) ? D2 : 0;
    int offy = (jy < D - 1) ? D  : 0;
    int offz = (jz < D - 1) ? 1  : 0;

    int r00 = bb + (jx << 14) + (jy << 7) + jz;     // base corner (000)
    int r01 = r00 + offy;
    int r10 = r00 + offx;
    int r11 = r10 + offy;

    // 8 corner fetches; each LDG.64 carries all 3 channels.
    uint2 v000 = __ldg(src + r00);
    uint2 v001 = __ldg(src + r00 + offz);
    uint2 v010 = __ldg(src + r01);
    uint2 v011 = __ldg(src + r01 + offz);
    uint2 v100 = __ldg(src + r10);
    uint2 v101 = __ldg(src + r10 + offz);
    uint2 v110 = __ldg(src + r11);
    uint2 v111 = __ldg(src + r11 + offz);

    float w00 = wx0 * wy0, w01 = wx0 * wy1, w10 = wx1 * wy0, w11 = wx1 * wy1;
    float w000 = w00 * wz0, w001 = w00 * wz1;
    float w010 = w01 * wz0, w011 = w01 * wz1;
    float w100 = w10 * wz0, w101 = w10 * wz1;
    float w110 = w11 * wz0, w111 = w11 * wz1;

    float ax = 0.f, ay = 0.f, az = 0.f, tx, ty, tz;
    unpackh4(v000, tx, ty, tz); ax = fmaf(w000, tx, ax); ay = fmaf(w000, ty, ay); az = fmaf(w000, tz, az);
    unpackh4(v001, tx, ty, tz); ax = fmaf(w001, tx, ax); ay = fmaf(w001, ty, ay); az = fmaf(w001, tz, az);
    unpackh4(v010, tx, ty, tz); ax = fmaf(w010, tx, ax); ay = fmaf(w010, ty, ay); az = fmaf(w010, tz, az);
    unpackh4(v011, tx, ty, tz); ax = fmaf(w011, tx, ax); ay = fmaf(w011, ty, ay); az = fmaf(w011, tz, az);
    unpackh4(v100, tx, ty, tz); ax = fmaf(w100, tx, ax); ay = fmaf(w100, ty, ay); az = fmaf(w100, tz, az);
    unpackh4(v101, tx, ty, tz); ax = fmaf(w101, tx, ax); ay = fmaf(w101, ty, ay); az = fmaf(w101, tz, az);
    unpackh4(v110, tx, ty, tz); ax = fmaf(w110, tx, ax); ay = fmaf(w110, ty, ay); az = fmaf(w110, tz, az);
    unpackh4(v111, tx, ty, tz); ax = fmaf(w111, tx, ax); ay = fmaf(w111, ty, ay); az = fmaf(w111, tz, az);

    float ox, oy, oz;
    if (SCALED) {
        ox = scale * (rx + ax);
        oy = scale * (ry + ay);
        oz = scale * (rz + az);
    } else {
        ox = rx + ax;
        oy = ry + ay;
        oz = rz + az;
    }

    if (OUT_F32_AOS) {
        float* dst = (float*)dst_raw;
        size_t o = (size_t)idx * 3;
        dst[o + 0] = ox;
        dst[o + 1] = oy;
        dst[o + 2] = oz;
    } else {
        ((uint2*)dst_raw)[idx] = packh4(ox, oy, oz);
    }
}

extern "C" void kernel_launch(void* const* d_in, const int* in_sizes, int n_in,
                              void* d_out, int out_size) {
    const float* dvf = (const float*)d_in[0];

    uint2* A = nullptr;
    uint2* Bf = nullptr;
    cudaGetSymbolAddress((void**)&A,  g_a);
    cudaGetSymbolAddress((void**)&Bf, g_b);

    const int nblocks = NVOX / NT;              // 16384
    const float s0 = 1.0f / 128.0f;             // 1 / 2^NUM_STEPS

    pack_h4<<<nblocks, NT>>>(dvf, A);

    intdvf_step<false, true ><<<nblocks, NT>>>(A,  Bf,   s0);   // step 1 (fused /128)
    intdvf_step<false, false><<<nblocks, NT>>>(Bf, A,    1.0f); // step 2
    intdvf_step<false, false><<<nblocks, NT>>>(A,  Bf,   1.0f); // step 3
    intdvf_step<false, false><<<nblocks, NT>>>(Bf, A,    1.0f); // step 4
    intdvf_step<false, false><<<nblocks, NT>>>(A,  Bf,   1.0f); // step 5
    intdvf_step<false, false><<<nblocks, NT>>>(Bf, A,    1.0f); // step 6
    intdvf_step<true,  false><<<nblocks, NT>>>(A,  d_out, 1.0f); // step 7 -> fp32 AoS
}

// round 16
// speedup vs baseline: 1.3873x; 1.0272x over previous
#include <cuda_runtime.h>
#include <cuda_fp16.h>

// IntDVF scaling-and-squaring, packed-half4, batch-paired ILP version.
// ddf0 = dvf / 2^7 ; repeat 7x: ddf = ddf + warp(ddf, ddf)
//
// Field stored as 4x fp16 (x,y,z,pad) = 8B/voxel (33.5 MB/buffer -> both
// ping-pong buffers L2-resident). Each thread processes the SAME (x,y,z)
// voxel in batch 0 and batch 1: shared index decode, 16 independent gather
// LDG.64s in flight to hide L2 latency (L1 pipe was 82.5% with idle gaps).
// fp32 arithmetic; fp16 storage only. Final step writes fp32 AoS to d_out.

#define D     128
#define D2    (D * D)
#define D3    (D * D * D)
#define NVOX  (2 * D3)          // 4,194,304 voxels (batch=2)
#define NT    256

// Two 33.5 MB packed ping-pong buffers (both L2-resident together).
__device__ uint2 g_a[(size_t)NVOX];
__device__ uint2 g_b[(size_t)NVOX];

__device__ __forceinline__ uint2 packh4(float x, float y, float z) {
    __half2 xy = __floats2half2_rn(x, y);
    __half2 zw = __floats2half2_rn(z, 0.0f);
    uint2 r;
    r.x = *(const unsigned int*)&xy;
    r.y = *(const unsigned int*)&zw;
    return r;
}

__device__ __forceinline__ void unpackh4(uint2 v, float& x, float& y, float& z) {
    __half2 xy = *(const __half2*)&v.x;
    __half2 zw = *(const __half2*)&v.y;
    float2 f = __half22float2(xy);
    x = f.x;
    y = f.y;
    z = __half2float(__low2half(zw));
}

__global__ __launch_bounds__(NT)
void pack_h4(const float* __restrict__ in, uint2* __restrict__ out) {
    int i = blockIdx.x * NT + threadIdx.x;
    size_t o = (size_t)i * 3;
    out[i] = packh4(in[o + 0], in[o + 1], in[o + 2]);
}

struct Tap {
    int r00, r01, r10, r11, offz;
    float w000, w001, w010, w011, w100, w101, w110, w111;
};

// Compute corner indices + weights for one voxel (no loads).
template<bool SCALED>
__device__ __forceinline__ Tap make_tap(
    int bb, float xf, float yf, float zf,
    float rx, float ry, float rz, float scale)
{
    float lx = xf + (SCALED ? rx * scale : rx);
    float ly = yf + (SCALED ? ry * scale : ry);
    float lz = zf + (SCALED ? rz * scale : rz);

    // Clamp the location (equivalent to the reference's index clipping).
    lx = fminf(fmaxf(lx, 0.0f), 127.0f);
    ly = fminf(fmaxf(ly, 0.0f), 127.0f);
    lz = fminf(fmaxf(lz, 0.0f), 127.0f);

    float fx = floorf(lx), fy = floorf(ly), fz = floorf(lz);
    float wx1 = lx - fx, wy1 = ly - fy, wz1 = lz - fz;
    float wx0 = 1.0f - wx1, wy0 = 1.0f - wy1, wz0 = 1.0f - wz1;

    int jx = (int)fx, jy = (int)fy, jz = (int)fz;   // all in [0,127]

    int offx = (jx < D - 1) ? D2 : 0;
    int offy = (jy < D - 1) ? D  : 0;

    Tap t;
    t.offz = (jz < D - 1) ? 1 : 0;
    t.r00 = bb + (jx << 14) + (jy << 7) + jz;
    t.r01 = t.r00 + offy;
    t.r10 = t.r00 + offx;
    t.r11 = t.r10 + offy;

    float w00 = wx0 * wy0, w01 = wx0 * wy1, w10 = wx1 * wy0, w11 = wx1 * wy1;
    t.w000 = w00 * wz0; t.w001 = w00 * wz1;
    t.w010 = w01 * wz0; t.w011 = w01 * wz1;
    t.w100 = w10 * wz0; t.w101 = w10 * wz1;
    t.w110 = w11 * wz0; t.w111 = w11 * wz1;
    return t;
}

__device__ __forceinline__ float3 gather_lerp(
    const uint2* __restrict__ src, const Tap& t)
{
    uint2 v000 = __ldg(src + t.r00);
    uint2 v001 = __ldg(src + t.r00 + t.offz);
    uint2 v010 = __ldg(src + t.r01);
    uint2 v011 = __ldg(src + t.r01 + t.offz);
    uint2 v100 = __ldg(src + t.r10);
    uint2 v101 = __ldg(src + t.r10 + t.offz);
    uint2 v110 = __ldg(src + t.r11);
    uint2 v111 = __ldg(src + t.r11 + t.offz);

    float ax = 0.f, ay = 0.f, az = 0.f, tx, ty, tz;
    unpackh4(v000, tx, ty, tz); ax = fmaf(t.w000, tx, ax); ay = fmaf(t.w000, ty, ay); az = fmaf(t.w000, tz, az);
    unpackh4(v001, tx, ty, tz); ax = fmaf(t.w001, tx, ax); ay = fmaf(t.w001, ty, ay); az = fmaf(t.w001, tz, az);
    unpackh4(v010, tx, ty, tz); ax = fmaf(t.w010, tx, ax); ay = fmaf(t.w010, ty, ay); az = fmaf(t.w010, tz, az);
    unpackh4(v011, tx, ty, tz); ax = fmaf(t.w011, tx, ax); ay = fmaf(t.w011, ty, ay); az = fmaf(t.w011, tz, az);
    unpackh4(v100, tx, ty, tz); ax = fmaf(t.w100, tx, ax); ay = fmaf(t.w100, ty, ay); az = fmaf(t.w100, tz, az);
    unpackh4(v101, tx, ty, tz); ax = fmaf(t.w101, tx, ax); ay = fmaf(t.w101, ty, ay); az = fmaf(t.w101, tz, az);
    unpackh4(v110, tx, ty, tz); ax = fmaf(t.w110, tx, ax); ay = fmaf(t.w110, ty, ay); az = fmaf(t.w110, tz, az);
    unpackh4(v111, tx, ty, tz); ax = fmaf(t.w111, tx, ax); ay = fmaf(t.w111, ty, ay); az = fmaf(t.w111, tz, az);
    return make_float3(ax, ay, az);
}

template<bool OUT_F32_AOS, bool SCALED>
__global__ __launch_bounds__(NT)
void intdvf_step(const uint2* __restrict__ src, void* __restrict__ dst_raw,
                 float scale) {
    int idx0 = blockIdx.x * NT + threadIdx.x;   // batch-0 voxel
    int idx1 = idx0 + D3;                       // same (x,y,z), batch 1
    int z = idx0 & (D - 1);
    int y = (idx0 >> 7) & (D - 1);
    int x = idx0 >> 14;                         // idx0 < D3 -> b=0

    float xf = (float)x, yf = (float)y, zf = (float)z;

    // Both center reads first (independent, in flight together).
    uint2 c0 = __ldg(src + idx0);
    uint2 c1 = __ldg(src + idx1);
    float rx0, ry0, rz0, rx1, ry1, rz1;
    unpackh4(c0, rx0, ry0, rz0);
    unpackh4(c1, rx1, ry1, rz1);

    Tap t0 = make_tap<SCALED>(0,  xf, yf, zf, rx0, ry0, rz0, scale);
    Tap t1 = make_tap<SCALED>(D3, xf, yf, zf, rx1, ry1, rz1, scale);

    // 16 independent gathers (compiler interleaves the two calls' loads).
    float3 a0 = gather_lerp(src, t0);
    float3 a1 = gather_lerp(src, t1);

    float ox0, oy0, oz0, ox1, oy1, oz1;
    if (SCALED) {
        ox0 = scale * (rx0 + a0.x); oy0 = scale * (ry0 + a0.y); oz0 = scale * (rz0 + a0.z);
        ox1 = scale * (rx1 + a1.x); oy1 = scale * (ry1 + a1.y); oz1 = scale * (rz1 + a1.z);
    } else {
        ox0 = rx0 + a0.x; oy0 = ry0 + a0.y; oz0 = rz0 + a0.z;
        ox1 = rx1 + a1.x; oy1 = ry1 + a1.y; oz1 = rz1 + a1.z;
    }

    if (OUT_F32_AOS) {
        float* dst = (float*)dst_raw;
        size_t o0 = (size_t)idx0 * 3;
        size_t o1 = (size_t)idx1 * 3;
        dst[o0 + 0] = ox0; dst[o0 + 1] = oy0; dst[o0 + 2] = oz0;
        dst[o1 + 0] = ox1; dst[o1 + 1] = oy1; dst[o1 + 2] = oz1;
    } else {
        uint2* d2 = (uint2*)dst_raw;
        d2[idx0] = packh4(ox0, oy0, oz0);
        d2[idx1] = packh4(ox1, oy1, oz1);
    }
}

extern "C" void kernel_launch(void* const* d_in, const int* in_sizes, int n_in,
                              void* d_out, int out_size) {
    const float* dvf = (const float*)d_in[0];

    uint2* A = nullptr;
    uint2* Bf = nullptr;
    cudaGetSymbolAddress((void**)&A,  g_a);
    cudaGetSymbolAddress((void**)&Bf, g_b);

    const int pack_blocks = NVOX / NT;          // 16384
    const int step_blocks = D3 / NT;            // 8192 (2 voxels/thread)
    const float s0 = 1.0f / 128.0f;             // 1 / 2^NUM_STEPS

    pack_h4<<<pack_blocks, NT>>>(dvf, A);

    intdvf_step<false, true ><<<step_blocks, NT>>>(A,  Bf,   s0);   // step 1 (fused /128)
    intdvf_step<false, false><<<step_blocks, NT>>>(Bf, A,    1.0f); // step 2
    intdvf_step<false, false><<<step_blocks, NT>>>(A,  Bf,   1.0f); // step 3
    intdvf_step<false, false><<<step_blocks, NT>>>(Bf, A,    1.0f); // step 4
    intdvf_step<false, false><<<step_blocks, NT>>>(A,  Bf,   1.0f); // step 5
    intdvf_step<false, false><<<step_blocks, NT>>>(Bf, A,    1.0f); // step 6
    intdvf_step<true,  false><<<step_blocks, NT>>>(A,  d_out, 1.0f); // step 7 -> fp32 AoS
}